// round 1
// baseline (speedup 1.0000x reference)
#include <cuda_runtime.h>

#define B_  8
#define T_  1024
#define DM_ 1024
#define H_  16
#define D_  64
#define BH_ (B_ * H_)
#define NEGV (-1.0e9f)

// Scratch (allocation-free rule: __device__ globals)
__device__ float g_qh[BH_ * T_ * D_];
__device__ float g_kh[BH_ * T_ * D_];
__device__ float g_vh[BH_ * T_ * D_];
__device__ float g_ctx[BH_ * T_ * D_];

// ---------------------------------------------------------------------------
// Kernel 1: projection GEMM.  C[m][n] = sum_k X[m][k] * W[n][k] + bias[n]
// M = B*T = 8192, N = 1024, K = 1024.  Output scattered to (B,H,T,D) layout.
// 128x128 block tile, K-chunk 16, 8x8 register micro-tile, 256 threads.
// ---------------------------------------------------------------------------
__global__ __launch_bounds__(256) void proj_kernel(
    const float* __restrict__ X, const float* __restrict__ W,
    const float* __restrict__ bias, float* __restrict__ out) {
    __shared__ float As[16][132];  // As[k][m], pad 132 (16B-aligned rows)
    __shared__ float Bs[16][132];  // Bs[k][n]

    const int m0 = blockIdx.y * 128;
    const int n0 = blockIdx.x * 128;
    const int tid = threadIdx.x;
    const int tx = tid & 15, ty = tid >> 4;

    float acc[8][8];
#pragma unroll
    for (int i = 0; i < 8; i++)
#pragma unroll
        for (int j = 0; j < 8; j++) acc[i][j] = 0.0f;

    for (int k0 = 0; k0 < DM_; k0 += 16) {
#pragma unroll
        for (int it = 0; it < 2; it++) {
            int lin = tid + it * 256;          // 512 float4 loads per operand
            int r = lin >> 2;                  // row within tile (0..127)
            int k4 = (lin & 3) << 2;           // k offset (0,4,8,12)
            float4 a = *reinterpret_cast<const float4*>(&X[(m0 + r) * DM_ + k0 + k4]);
            As[k4 + 0][r] = a.x; As[k4 + 1][r] = a.y;
            As[k4 + 2][r] = a.z; As[k4 + 3][r] = a.w;
            float4 b = *reinterpret_cast<const float4*>(&W[(n0 + r) * DM_ + k0 + k4]);
            Bs[k4 + 0][r] = b.x; Bs[k4 + 1][r] = b.y;
            Bs[k4 + 2][r] = b.z; Bs[k4 + 3][r] = b.w;
        }
        __syncthreads();
#pragma unroll
        for (int kk = 0; kk < 16; kk++) {
            float a[8], b[8];
            float4 t;
            t = *reinterpret_cast<const float4*>(&As[kk][ty * 8]);
            a[0] = t.x; a[1] = t.y; a[2] = t.z; a[3] = t.w;
            t = *reinterpret_cast<const float4*>(&As[kk][ty * 8 + 4]);
            a[4] = t.x; a[5] = t.y; a[6] = t.z; a[7] = t.w;
            t = *reinterpret_cast<const float4*>(&Bs[kk][tx * 8]);
            b[0] = t.x; b[1] = t.y; b[2] = t.z; b[3] = t.w;
            t = *reinterpret_cast<const float4*>(&Bs[kk][tx * 8 + 4]);
            b[4] = t.x; b[5] = t.y; b[6] = t.z; b[7] = t.w;
#pragma unroll
            for (int i = 0; i < 8; i++)
#pragma unroll
                for (int j = 0; j < 8; j++) acc[i][j] += a[i] * b[j];
        }
        __syncthreads();
    }

    // Epilogue: add bias, scatter to (B,H,T,D)
#pragma unroll
    for (int i = 0; i < 8; i++) {
        int m = m0 + ty * 8 + i;
        int bb = m >> 10, t = m & 1023;
#pragma unroll
        for (int jj = 0; jj < 2; jj++) {
            int n = n0 + tx * 8 + jj * 4;
            int h = n >> 6, dd = n & 63;
            float4 o;
            o.x = acc[i][jj * 4 + 0] + bias[n + 0];
            o.y = acc[i][jj * 4 + 1] + bias[n + 1];
            o.z = acc[i][jj * 4 + 2] + bias[n + 2];
            o.w = acc[i][jj * 4 + 3] + bias[n + 3];
            *reinterpret_cast<float4*>(&out[((bb * H_ + h) * T_ + t) * D_ + dd]) = o;
        }
    }
}

// ---------------------------------------------------------------------------
// Kernel 2: attention per (head bh, 64-row q-tile).
// Pass 1: stream K tiles, online row max/sum.
// Pass 2: recompute scores, p = exp(s-m)/l, write attn, ctx += p @ V.
// smem: Qs[d][q] (pad 68), Ks[d][kc] (pad 68, reused as Pt[kc][q]), Vs[kc][d].
// ---------------------------------------------------------------------------
__global__ __launch_bounds__(256) void attn_kernel(
    const int* __restrict__ mask, float* __restrict__ attn_out) {
    extern __shared__ float smdyn[];
    float* Qs = smdyn;                 // 64*68
    float* Ks = smdyn + 64 * 68;       // 64*68  (reused as Pt)
    float* Vs = smdyn + 2 * 64 * 68;   // 64*64
    __shared__ float sm_m[64];
    __shared__ float sm_l[64];

    const int bh = blockIdx.x;
    const int q0 = blockIdx.y * 64;
    const int tid = threadIdx.x;
    const int tx = tid & 15, ty = tid >> 4;

    // Load Q tile transposed & pre-scaled by 1/sqrt(D)
#pragma unroll
    for (int it = 0; it < 4; it++) {
        int lin = tid + it * 256;
        int r = lin >> 4;
        int d4 = (lin & 15) << 2;
        float4 v = *reinterpret_cast<const float4*>(&g_qh[(bh * T_ + q0 + r) * D_ + d4]);
        Qs[(d4 + 0) * 68 + r] = v.x * 0.125f;
        Qs[(d4 + 1) * 68 + r] = v.y * 0.125f;
        Qs[(d4 + 2) * 68 + r] = v.z * 0.125f;
        Qs[(d4 + 3) * 68 + r] = v.w * 0.125f;
    }
    if (tid < 64) { sm_m[tid] = -1e30f; sm_l[tid] = 0.0f; }
    __syncthreads();

    // ---------------- Pass 1: row max & sum ----------------
    for (int kt = 0; kt < T_; kt += 64) {
#pragma unroll
        for (int it = 0; it < 4; it++) {
            int lin = tid + it * 256;
            int r = lin >> 4;
            int d4 = (lin & 15) << 2;
            float4 v = *reinterpret_cast<const float4*>(&g_kh[(bh * T_ + kt + r) * D_ + d4]);
            Ks[(d4 + 0) * 68 + r] = v.x;
            Ks[(d4 + 1) * 68 + r] = v.y;
            Ks[(d4 + 2) * 68 + r] = v.z;
            Ks[(d4 + 3) * 68 + r] = v.w;
        }
        __syncthreads();

        float s[4][4];
#pragma unroll
        for (int i = 0; i < 4; i++)
#pragma unroll
            for (int j = 0; j < 4; j++) s[i][j] = 0.0f;
#pragma unroll
        for (int kk = 0; kk < 64; kk++) {
            float4 a4 = *reinterpret_cast<const float4*>(&Qs[kk * 68 + ty * 4]);
            float4 b4 = *reinterpret_cast<const float4*>(&Ks[kk * 68 + tx * 4]);
            float a[4] = {a4.x, a4.y, a4.z, a4.w};
            float b[4] = {b4.x, b4.y, b4.z, b4.w};
#pragma unroll
            for (int i = 0; i < 4; i++)
#pragma unroll
                for (int j = 0; j < 4; j++) s[i][j] += a[i] * b[j];
        }
#pragma unroll
        for (int i = 0; i < 4; i++) {
            int4 mm = *reinterpret_cast<const int4*>(&mask[(q0 + ty * 4 + i) * T_ + kt + tx * 4]);
            if (mm.x == 0) s[i][0] = NEGV;
            if (mm.y == 0) s[i][1] = NEGV;
            if (mm.z == 0) s[i][2] = NEGV;
            if (mm.w == 0) s[i][3] = NEGV;
        }
#pragma unroll
        for (int i = 0; i < 4; i++) {
            int q = ty * 4 + i;
            float tm = fmaxf(fmaxf(s[i][0], s[i][1]), fmaxf(s[i][2], s[i][3]));
#pragma unroll
            for (int off = 8; off; off >>= 1)
                tm = fmaxf(tm, __shfl_xor_sync(0xffffffffu, tm, off));
            float mo = sm_m[q];
            float mn = fmaxf(mo, tm);
            float le = __expf(s[i][0] - mn) + __expf(s[i][1] - mn) +
                       __expf(s[i][2] - mn) + __expf(s[i][3] - mn);
#pragma unroll
            for (int off = 8; off; off >>= 1)
                le += __shfl_xor_sync(0xffffffffu, le, off);
            if (tx == 0) {
                sm_l[q] = sm_l[q] * __expf(mo - mn) + le;
                sm_m[q] = mn;
            }
        }
        __syncthreads();
    }

    float mrow[4], linv[4];
#pragma unroll
    for (int i = 0; i < 4; i++) {
        int q = ty * 4 + i;
        mrow[i] = sm_m[q];
        linv[i] = 1.0f / sm_l[q];
    }

    // ---------------- Pass 2: attn write + ctx accumulate ----------------
    float c[4][4];
#pragma unroll
    for (int i = 0; i < 4; i++)
#pragma unroll
        for (int j = 0; j < 4; j++) c[i][j] = 0.0f;

    for (int kt = 0; kt < T_; kt += 64) {
        __syncthreads();  // prior iteration's Pt/Vs reads complete
#pragma unroll
        for (int it = 0; it < 4; it++) {
            int lin = tid + it * 256;
            int r = lin >> 4;
            int d4 = (lin & 15) << 2;
            float4 v = *reinterpret_cast<const float4*>(&g_kh[(bh * T_ + kt + r) * D_ + d4]);
            Ks[(d4 + 0) * 68 + r] = v.x;
            Ks[(d4 + 1) * 68 + r] = v.y;
            Ks[(d4 + 2) * 68 + r] = v.z;
            Ks[(d4 + 3) * 68 + r] = v.w;
            float4 vv = *reinterpret_cast<const float4*>(&g_vh[(bh * T_ + kt + r) * D_ + d4]);
            *reinterpret_cast<float4*>(&Vs[r * 64 + d4]) = vv;
        }
        __syncthreads();

        float s[4][4];
#pragma unroll
        for (int i = 0; i < 4; i++)
#pragma unroll
            for (int j = 0; j < 4; j++) s[i][j] = 0.0f;
#pragma unroll
        for (int kk = 0; kk < 64; kk++) {
            float4 a4 = *reinterpret_cast<const float4*>(&Qs[kk * 68 + ty * 4]);
            float4 b4 = *reinterpret_cast<const float4*>(&Ks[kk * 68 + tx * 4]);
            float a[4] = {a4.x, a4.y, a4.z, a4.w};
            float b[4] = {b4.x, b4.y, b4.z, b4.w};
#pragma unroll
            for (int i = 0; i < 4; i++)
#pragma unroll
                for (int j = 0; j < 4; j++) s[i][j] += a[i] * b[j];
        }
#pragma unroll
        for (int i = 0; i < 4; i++) {
            int4 mm = *reinterpret_cast<const int4*>(&mask[(q0 + ty * 4 + i) * T_ + kt + tx * 4]);
            if (mm.x == 0) s[i][0] = NEGV;
            if (mm.y == 0) s[i][1] = NEGV;
            if (mm.z == 0) s[i][2] = NEGV;
            if (mm.w == 0) s[i][3] = NEGV;
        }
        float p[4][4];
#pragma unroll
        for (int i = 0; i < 4; i++)
#pragma unroll
            for (int j = 0; j < 4; j++)
                p[i][j] = __expf(s[i][j] - mrow[i]) * linv[i];

        if (attn_out) {
#pragma unroll
            for (int i = 0; i < 4; i++) {
                float4 o = make_float4(p[i][0], p[i][1], p[i][2], p[i][3]);
                *reinterpret_cast<float4*>(
                    &attn_out[(bh * T_ + q0 + ty * 4 + i) * T_ + kt + tx * 4]) = o;
            }
        }
        __syncthreads();  // score reads of Ks done; safe to overwrite as Pt
#pragma unroll
        for (int i = 0; i < 4; i++)
#pragma unroll
            for (int j = 0; j < 4; j++)
                Ks[(tx * 4 + j) * 68 + ty * 4 + i] = p[i][j];  // Pt[kc][q]
        __syncthreads();
#pragma unroll
        for (int kk = 0; kk < 64; kk++) {
            float4 a4 = *reinterpret_cast<const float4*>(&Ks[kk * 68 + ty * 4]);
            float4 b4 = *reinterpret_cast<const float4*>(&Vs[kk * 64 + tx * 4]);
            float a[4] = {a4.x, a4.y, a4.z, a4.w};
            float b[4] = {b4.x, b4.y, b4.z, b4.w};
#pragma unroll
            for (int i = 0; i < 4; i++)
#pragma unroll
                for (int j = 0; j < 4; j++) c[i][j] += a[i] * b[j];
        }
    }

#pragma unroll
    for (int i = 0; i < 4; i++) {
        float4 o = make_float4(c[i][0], c[i][1], c[i][2], c[i][3]);
        *reinterpret_cast<float4*>(&g_ctx[(bh * T_ + q0 + ty * 4 + i) * D_ + tx * 4]) = o;
    }
}

// ---------------------------------------------------------------------------
// Kernel 3: out = gather(ctx) @ Wo^T + bo.  M=8192, N=64, K=1024 (h*64+d).
// ---------------------------------------------------------------------------
__global__ __launch_bounds__(256) void outproj_kernel(
    const float* __restrict__ Wo, const float* __restrict__ bo,
    float* __restrict__ out) {
    __shared__ float As[64][65];  // As[m][d]
    __shared__ float Bs[64][65];  // Bs[n][d]
    const int m0 = blockIdx.x * 64;
    const int tid = threadIdx.x;
    const int tx = tid & 15, ty = tid >> 4;

    float acc[4][4];
#pragma unroll
    for (int i = 0; i < 4; i++)
#pragma unroll
        for (int j = 0; j < 4; j++) acc[i][j] = 0.0f;

    for (int h = 0; h < H_; h++) {
#pragma unroll
        for (int it = 0; it < 4; it++) {
            int lin = tid + it * 256;
            int r = lin >> 4;
            int d4 = (lin & 15) << 2;
            int m = m0 + r;
            int bb = m >> 10, t = m & 1023;
            float4 a = *reinterpret_cast<const float4*>(
                &g_ctx[((bb * H_ + h) * T_ + t) * D_ + d4]);
            As[r][d4 + 0] = a.x; As[r][d4 + 1] = a.y;
            As[r][d4 + 2] = a.z; As[r][d4 + 3] = a.w;
            float4 b = *reinterpret_cast<const float4*>(&Wo[r * DM_ + h * D_ + d4]);
            Bs[r][d4 + 0] = b.x; Bs[r][d4 + 1] = b.y;
            Bs[r][d4 + 2] = b.z; Bs[r][d4 + 3] = b.w;
        }
        __syncthreads();
#pragma unroll
        for (int kk = 0; kk < 64; kk++) {
            float a[4], b[4];
#pragma unroll
            for (int i = 0; i < 4; i++) a[i] = As[ty * 4 + i][kk];
#pragma unroll
            for (int j = 0; j < 4; j++) b[j] = Bs[tx * 4 + j][kk];
#pragma unroll
            for (int i = 0; i < 4; i++)
#pragma unroll
                for (int j = 0; j < 4; j++) acc[i][j] += a[i] * b[j];
        }
        __syncthreads();
    }
#pragma unroll
    for (int i = 0; i < 4; i++) {
        float4 o;
        o.x = acc[i][0] + bo[tx * 4 + 0];
        o.y = acc[i][1] + bo[tx * 4 + 1];
        o.z = acc[i][2] + bo[tx * 4 + 2];
        o.w = acc[i][3] + bo[tx * 4 + 3];
        *reinterpret_cast<float4*>(&out[(m0 + ty * 4 + i) * D_ + tx * 4]) = o;
    }
}

// ---------------------------------------------------------------------------

extern "C" void kernel_launch(void* const* d_in, const int* in_sizes, int n_in,
                              void* d_out, int out_size) {
    const float* q  = (const float*)d_in[0];
    const float* k  = (const float*)d_in[1];
    const float* v  = (const float*)d_in[2];
    const float* Wq = (const float*)d_in[3];
    const float* bq = (const float*)d_in[4];
    const float* Wk = (const float*)d_in[5];
    const float* bk = (const float*)d_in[6];
    const float* Wv = (const float*)d_in[7];
    const float* bv = (const float*)d_in[8];
    const float* Wo = (const float*)d_in[9];
    const float* bo = (const float*)d_in[10];
    const int* mask = (const int*)d_in[11];

    float* out = (float*)d_out;
    const long long OUTN  = (long long)B_ * T_ * D_;          // 524288
    const long long ATTNN = (long long)BH_ * T_ * T_;         // 134217728
    float* attn = ((long long)out_size >= OUTN + ATTNN) ? (out + OUTN) : nullptr;

    float *qh, *kh, *vh;
    cudaGetSymbolAddress((void**)&qh, g_qh);
    cudaGetSymbolAddress((void**)&kh, g_kh);
    cudaGetSymbolAddress((void**)&vh, g_vh);

    dim3 gp(DM_ / 128, (B_ * T_) / 128);
    proj_kernel<<<gp, 256>>>(q, Wq, bq, qh);
    proj_kernel<<<gp, 256>>>(k, Wk, bk, kh);
    proj_kernel<<<gp, 256>>>(v, Wv, bv, vh);

    const int ATTN_SMEM = (2 * 64 * 68 + 64 * 64) * (int)sizeof(float);  // 51200
    cudaFuncSetAttribute(attn_kernel, cudaFuncAttributeMaxDynamicSharedMemorySize,
                         ATTN_SMEM);
    attn_kernel<<<dim3(BH_, T_ / 64), 256, ATTN_SMEM>>>(mask, attn);

    outproj_kernel<<<(B_ * T_) / 64, 256>>>(Wo, bo, out);
}